// round 3
// baseline (speedup 1.0000x reference)
#include <cuda_runtime.h>
#include <cuda_bf16.h>

#define H     128
#define NSEG  512
#define RANKS 3
#define LN_EPS 1e-5f

// ---------------- scratch (no allocations allowed) ----------------
__device__ float g_sum [RANKS * NSEG * H];
__device__ float g_gsum[RANKS * NSEG * H];
__device__ float g_max [RANKS * NSEG * H];
__device__ float g_cnt [RANKS * NSEG];
__device__ float g_r   [RANKS * NSEG * H];

// ---------------- helpers ----------------
__device__ __forceinline__ void atomicMaxF(float* addr, float v) {
    if (v >= 0.f) atomicMax((int*)addr, __float_as_int(v));
    else          atomicMin((unsigned int*)addr, __float_as_uint(v));
}

__device__ __forceinline__ float warp_sum(float v) {
    v += __shfl_xor_sync(0xffffffffu, v, 16);
    v += __shfl_xor_sync(0xffffffffu, v, 8);
    v += __shfl_xor_sync(0xffffffffu, v, 4);
    v += __shfl_xor_sync(0xffffffffu, v, 2);
    v += __shfl_xor_sync(0xffffffffu, v, 1);
    return v;
}

// ---------------- 1. zero accumulators ----------------
__global__ void zero_kernel() {
    int i = blockIdx.x * blockDim.x + threadIdx.x;
    if (i < RANKS * NSEG * H) {
        g_sum[i]  = 0.f;
        g_gsum[i] = 0.f;
        g_max[i]  = __int_as_float(0xff800000);  // -inf
    }
    if (i < RANKS * NSEG) g_cnt[i] = 0.f;
}

// ---------------- 2. single-pass gated multi-aggregation ----------------
// Warp-per-contiguous-chunk. Lane holds float4 of columns [4*lane, 4*lane+4).
__global__ __launch_bounds__(256) void agg_kernel(
    const float* __restrict__ h0, const float* __restrict__ h1, const float* __restrict__ h2,
    const int*   __restrict__ b0, const int*   __restrict__ b1, const int*   __restrict__ b2,
    const float* __restrict__ Wg0, const float* __restrict__ Wg1, const float* __restrict__ Wg2,
    const float* __restrict__ bg0, const float* __restrict__ bg1, const float* __restrict__ bg2,
    int N0, int N1, int N2)
{
    const int rank = blockIdx.y;
    const float* h;  const int* b;  const float* Wg;  float bg;  int N;
    if (rank == 0)      { h = h0; b = b0; Wg = Wg0; bg = bg0[0]; N = N0; }
    else if (rank == 1) { h = h1; b = b1; Wg = Wg1; bg = bg1[0]; N = N1; }
    else                { h = h2; b = b2; Wg = Wg2; bg = bg2[0]; N = N2; }

    const int lane          = threadIdx.x & 31;
    const int warpsPerBlock = blockDim.x >> 5;
    const int gw            = blockIdx.x * warpsPerBlock + (threadIdx.x >> 5);
    const int totalWarps    = gridDim.x * warpsPerBlock;
    const int chunk         = (N + totalWarps - 1) / totalWarps;
    const int start         = gw * chunk;
    const int end           = min(start + chunk, N);
    if (start >= end) return;

    const float4 wg  = reinterpret_cast<const float4*>(Wg)[lane];
    const float  NEG = __int_as_float(0xff800000);

    float4 s  = make_float4(0.f, 0.f, 0.f, 0.f);
    float4 gs = make_float4(0.f, 0.f, 0.f, 0.f);
    float4 mx = make_float4(NEG, NEG, NEG, NEG);
    float  cnt = 0.f;

    int    cur = __ldg(&b[start]);
    int    seg = cur;
    float4 hv  = reinterpret_cast<const float4*>(h + (size_t)start * H)[lane];

    for (int row = start; row < end; ++row) {
        // prefetch next row (software pipeline, MLP>=2)
        float4 hn; int sn = 0;
        if (row + 1 < end) {
            hn = reinterpret_cast<const float4*>(h + (size_t)(row + 1) * H)[lane];
            sn = __ldg(&b[row + 1]);
        }

        if (seg != cur) {
            // flush accumulators for finished segment
            const int base = (rank * NSEG + cur) * H + lane * 4;
            atomicAdd(&g_sum[base + 0], s.x);  atomicAdd(&g_sum[base + 1], s.y);
            atomicAdd(&g_sum[base + 2], s.z);  atomicAdd(&g_sum[base + 3], s.w);
            atomicAdd(&g_gsum[base + 0], gs.x); atomicAdd(&g_gsum[base + 1], gs.y);
            atomicAdd(&g_gsum[base + 2], gs.z); atomicAdd(&g_gsum[base + 3], gs.w);
            atomicMaxF(&g_max[base + 0], mx.x); atomicMaxF(&g_max[base + 1], mx.y);
            atomicMaxF(&g_max[base + 2], mx.z); atomicMaxF(&g_max[base + 3], mx.w);
            if (lane == 0) atomicAdd(&g_cnt[rank * NSEG + cur], cnt);
            s  = make_float4(0.f, 0.f, 0.f, 0.f);
            gs = make_float4(0.f, 0.f, 0.f, 0.f);
            mx = make_float4(NEG, NEG, NEG, NEG);
            cnt = 0.f;
            cur = seg;
        }

        // gate: sigmoid(h . Wg + bg) — full-warp dot via butterfly
        float p = hv.x * wg.x + hv.y * wg.y + hv.z * wg.z + hv.w * wg.w;
        p = warp_sum(p);
        const float g = 1.f / (1.f + __expf(-(p + bg)));

        s.x += hv.x; s.y += hv.y; s.z += hv.z; s.w += hv.w;
        gs.x = fmaf(g, hv.x, gs.x); gs.y = fmaf(g, hv.y, gs.y);
        gs.z = fmaf(g, hv.z, gs.z); gs.w = fmaf(g, hv.w, gs.w);
        mx.x = fmaxf(mx.x, hv.x);  mx.y = fmaxf(mx.y, hv.y);
        mx.z = fmaxf(mx.z, hv.z);  mx.w = fmaxf(mx.w, hv.w);
        cnt += 1.f;

        hv  = hn;
        seg = sn;
    }

    // final flush
    const int base = (rank * NSEG + cur) * H + lane * 4;
    atomicAdd(&g_sum[base + 0], s.x);  atomicAdd(&g_sum[base + 1], s.y);
    atomicAdd(&g_sum[base + 2], s.z);  atomicAdd(&g_sum[base + 3], s.w);
    atomicAdd(&g_gsum[base + 0], gs.x); atomicAdd(&g_gsum[base + 1], gs.y);
    atomicAdd(&g_gsum[base + 2], gs.z); atomicAdd(&g_gsum[base + 3], gs.w);
    atomicMaxF(&g_max[base + 0], mx.x); atomicMaxF(&g_max[base + 1], mx.y);
    atomicMaxF(&g_max[base + 2], mx.z); atomicMaxF(&g_max[base + 3], mx.w);
    if (lane == 0) atomicAdd(&g_cnt[rank * NSEG + cur], cnt);
}

// ---------------- 3. per-rank projection: agg[B,4H] @ Wp[4H,H] + bp ----------------
__global__ __launch_bounds__(128) void proj_kernel(
    const float* __restrict__ Wp0, const float* __restrict__ bp0,
    const float* __restrict__ Wp1, const float* __restrict__ bp1,
    const float* __restrict__ Wp2, const float* __restrict__ bp2)
{
    const int rank = blockIdx.y;
    const int seg  = blockIdx.x;
    const int j    = threadIdx.x;

    const float* Wp = (rank == 0) ? Wp0 : (rank == 1) ? Wp1 : Wp2;
    const float* bp = (rank == 0) ? bp0 : (rank == 1) ? bp1 : bp2;

    __shared__ float agg[4 * H];

    const int   base = (rank * NSEG + seg) * H;
    const float cnt  = g_cnt[rank * NSEG + seg];
    const float sv   = g_sum[base + j];
    const float mv   = g_max[base + j];

    agg[j]         = sv;
    agg[H + j]     = sv / fmaxf(cnt, 1.f);
    agg[2 * H + j] = (cnt > 0.f) ? mv : 0.f;
    agg[3 * H + j] = g_gsum[base + j];
    __syncthreads();

    float acc = bp[j];
#pragma unroll 8
    for (int k = 0; k < 4 * H; ++k)
        acc = fmaf(agg[k], Wp[k * H + j], acc);

    g_r[base + j] = acc;
}

// ---------------- 4. head: concat -> LayerNorm -> SiLU -> W1 -> SiLU -> W2 ----------------
__global__ __launch_bounds__(128) void head_kernel(
    const float* __restrict__ gamma, const float* __restrict__ beta,
    const float* __restrict__ W1,    const float* __restrict__ b1f,
    const float* __restrict__ W2,    const float* __restrict__ b2f,
    float* __restrict__ out)
{
    const int seg = blockIdx.x;
    const int t   = threadIdx.x;

    __shared__ float sx[3 * H];
    __shared__ float red[4];

    const float v0 = g_r[(0 * NSEG + seg) * H + t];
    const float v1 = g_r[(1 * NSEG + seg) * H + t];
    const float v2 = g_r[(2 * NSEG + seg) * H + t];

    // mean
    float loc = warp_sum(v0 + v1 + v2);
    if ((t & 31) == 0) red[t >> 5] = loc;
    __syncthreads();
    const float mu = (red[0] + red[1] + red[2] + red[3]) * (1.f / (3.f * H));
    __syncthreads();

    // variance (two-pass)
    const float d0 = v0 - mu, d1 = v1 - mu, d2 = v2 - mu;
    float loc2 = warp_sum(d0 * d0 + d1 * d1 + d2 * d2);
    if ((t & 31) == 0) red[t >> 5] = loc2;
    __syncthreads();
    const float var  = (red[0] + red[1] + red[2] + red[3]) * (1.f / (3.f * H));
    const float rstd = rsqrtf(var + LN_EPS);
    __syncthreads();

    // normalize + SiLU into shared
    {
        float xn0 = d0 * rstd * gamma[t]         + beta[t];
        float xn1 = d1 * rstd * gamma[H + t]     + beta[H + t];
        float xn2 = d2 * rstd * gamma[2 * H + t] + beta[2 * H + t];
        sx[t]         = xn0 / (1.f + __expf(-xn0));
        sx[H + t]     = xn1 / (1.f + __expf(-xn1));
        sx[2 * H + t] = xn2 / (1.f + __expf(-xn2));
    }
    __syncthreads();

    // x @ W1 + b1f -> SiLU
    float acc = b1f[t];
#pragma unroll 8
    for (int k = 0; k < 3 * H; ++k)
        acc = fmaf(sx[k], W1[k * H + t], acc);
    const float x2 = acc / (1.f + __expf(-acc));

    // dot with W2 -> out[seg]
    float o = warp_sum(x2 * W2[t]);
    if ((t & 31) == 0) red[t >> 5] = o;
    __syncthreads();
    if (t == 0)
        out[seg] = red[0] + red[1] + red[2] + red[3] + b2f[0];
}

// ---------------- launcher ----------------
extern "C" void kernel_launch(void* const* d_in, const int* in_sizes, int n_in,
                              void* d_out, int out_size)
{
    const float* h0  = (const float*)d_in[0];
    const float* h1  = (const float*)d_in[1];
    const float* h2  = (const float*)d_in[2];
    const int*   b0  = (const int*)  d_in[3];
    const int*   b1  = (const int*)  d_in[4];
    const int*   b2  = (const int*)  d_in[5];
    const float* Wg0 = (const float*)d_in[6];
    const float* bg0 = (const float*)d_in[7];
    const float* Wg1 = (const float*)d_in[8];
    const float* bg1 = (const float*)d_in[9];
    const float* Wg2 = (const float*)d_in[10];
    const float* bg2 = (const float*)d_in[11];
    const float* Wp0 = (const float*)d_in[12];
    const float* bp0 = (const float*)d_in[13];
    const float* Wp1 = (const float*)d_in[14];
    const float* bp1 = (const float*)d_in[15];
    const float* Wp2 = (const float*)d_in[16];
    const float* bp2 = (const float*)d_in[17];
    const float* gamma = (const float*)d_in[18];
    const float* beta  = (const float*)d_in[19];
    const float* W1    = (const float*)d_in[20];
    const float* b1f   = (const float*)d_in[21];
    const float* W2    = (const float*)d_in[22];
    const float* b2f   = (const float*)d_in[23];

    const int N0 = in_sizes[3];
    const int N1 = in_sizes[4];
    const int N2 = in_sizes[5];

    // 1. zero segment accumulators
    zero_kernel<<<(RANKS * NSEG * H + 255) / 256, 256>>>();

    // 2. single bandwidth pass over all node features
    dim3 gAgg(256, RANKS);
    agg_kernel<<<gAgg, 256>>>(h0, h1, h2, b0, b1, b2,
                              Wg0, Wg1, Wg2, bg0, bg1, bg2,
                              N0, N1, N2);

    // 3. per-rank pooled projection
    dim3 gProj(NSEG, RANKS);
    proj_kernel<<<gProj, 128>>>(Wp0, bp0, Wp1, bp1, Wp2, bp2);

    // 4. head
    head_kernel<<<NSEG, 128>>>(gamma, beta, W1, b1f, W2, b2f, (float*)d_out);
}

// round 4
// speedup vs baseline: 1.5276x; 1.5276x over previous
#include <cuda_runtime.h>
#include <cuda_bf16.h>

#define H     128
#define NSEG  512
#define RANKS 3
#define LN_EPS 1e-5f
#define U     8      // rows per group in agg kernel

// ---------------- scratch (no allocations allowed) ----------------
__device__ float g_sum [RANKS * NSEG * H];
__device__ float g_gsum[RANKS * NSEG * H];
__device__ float g_max [RANKS * NSEG * H];
__device__ float g_cnt [RANKS * NSEG];
__device__ float g_r   [RANKS * NSEG * H];

// ---------------- helpers ----------------
__device__ __forceinline__ void atomicMaxF(float* addr, float v) {
    if (v >= 0.f) atomicMax((int*)addr, __float_as_int(v));
    else          atomicMin((unsigned int*)addr, __float_as_uint(v));
}

__device__ __forceinline__ float warp_sum(float v) {
    v += __shfl_xor_sync(0xffffffffu, v, 16);
    v += __shfl_xor_sync(0xffffffffu, v, 8);
    v += __shfl_xor_sync(0xffffffffu, v, 4);
    v += __shfl_xor_sync(0xffffffffu, v, 2);
    v += __shfl_xor_sync(0xffffffffu, v, 1);
    return v;
}

// ---------------- 1. zero accumulators ----------------
__global__ void zero_kernel() {
    int i = blockIdx.x * blockDim.x + threadIdx.x;
    if (i < RANKS * NSEG * H) {
        g_sum[i]  = 0.f;
        g_gsum[i] = 0.f;
        g_max[i]  = __int_as_float(0xff800000);  // -inf
    }
    if (i < RANKS * NSEG) g_cnt[i] = 0.f;
}

// ---------------- 2. single-pass gated multi-aggregation ----------------
// Warp-per-contiguous-chunk; 8-row groups for MLP=8 and interleaved butterflies.
__global__ __launch_bounds__(256) void agg_kernel(
    const float* __restrict__ h0, const float* __restrict__ h1, const float* __restrict__ h2,
    const int*   __restrict__ b0, const int*   __restrict__ b1, const int*   __restrict__ b2,
    const float* __restrict__ Wg0, const float* __restrict__ Wg1, const float* __restrict__ Wg2,
    const float* __restrict__ bg0, const float* __restrict__ bg1, const float* __restrict__ bg2,
    int N0, int N1, int N2)
{
    const int rank = blockIdx.y;
    const float* h;  const int* b;  const float* Wg;  float bg;  int N;
    if (rank == 0)      { h = h0; b = b0; Wg = Wg0; bg = bg0[0]; N = N0; }
    else if (rank == 1) { h = h1; b = b1; Wg = Wg1; bg = bg1[0]; N = N1; }
    else                { h = h2; b = b2; Wg = Wg2; bg = bg2[0]; N = N2; }

    const int lane          = threadIdx.x & 31;
    const int warpsPerBlock = blockDim.x >> 5;
    const int gw            = blockIdx.x * warpsPerBlock + (threadIdx.x >> 5);
    const int totalWarps    = gridDim.x * warpsPerBlock;
    const int chunk         = (N + totalWarps - 1) / totalWarps;
    const int start         = gw * chunk;
    const int end           = min(start + chunk, N);
    if (start >= end) return;

    const float4 wg  = reinterpret_cast<const float4*>(Wg)[lane];
    const float  NEG = __int_as_float(0xff800000);

    float4 s  = make_float4(0.f, 0.f, 0.f, 0.f);
    float4 gs = make_float4(0.f, 0.f, 0.f, 0.f);
    float4 mx = make_float4(NEG, NEG, NEG, NEG);
    float  cnt = 0.f;
    int    cur = __ldg(&b[start]);

    // flush macro (accumulators -> global atomics)
    #define FLUSH()                                                          \
    do {                                                                     \
        const int _base = (rank * NSEG + cur) * H + lane * 4;                \
        atomicAdd(&g_sum [_base + 0], s.x);  atomicAdd(&g_sum [_base + 1], s.y);  \
        atomicAdd(&g_sum [_base + 2], s.z);  atomicAdd(&g_sum [_base + 3], s.w);  \
        atomicAdd(&g_gsum[_base + 0], gs.x); atomicAdd(&g_gsum[_base + 1], gs.y); \
        atomicAdd(&g_gsum[_base + 2], gs.z); atomicAdd(&g_gsum[_base + 3], gs.w); \
        atomicMaxF(&g_max[_base + 0], mx.x); atomicMaxF(&g_max[_base + 1], mx.y); \
        atomicMaxF(&g_max[_base + 2], mx.z); atomicMaxF(&g_max[_base + 3], mx.w); \
        if (lane == 0) atomicAdd(&g_cnt[rank * NSEG + cur], cnt);            \
        s  = make_float4(0.f, 0.f, 0.f, 0.f);                                \
        gs = make_float4(0.f, 0.f, 0.f, 0.f);                                \
        mx = make_float4(NEG, NEG, NEG, NEG);                                \
        cnt = 0.f;                                                           \
    } while (0)

    int row = start;

    // main loop: groups of U rows, fully resident
    for (; row + U <= end; row += U) {
        float4 hv[U];
        int    sg[U];
        float  p[U];
        #pragma unroll
        for (int i = 0; i < U; ++i) {
            hv[i] = reinterpret_cast<const float4*>(h + (size_t)(row + i) * H)[lane];
            sg[i] = __ldg(&b[row + i]);
        }
        #pragma unroll
        for (int i = 0; i < U; ++i)
            p[i] = hv[i].x * wg.x + hv[i].y * wg.y + hv[i].z * wg.z + hv[i].w * wg.w;

        // interleaved butterflies: 8 independent reductions share latency
        #pragma unroll
        for (int off = 16; off; off >>= 1) {
            #pragma unroll
            for (int i = 0; i < U; ++i)
                p[i] += __shfl_xor_sync(0xffffffffu, p[i], off);
        }

        #pragma unroll
        for (int i = 0; i < U; ++i) {
            if (sg[i] != cur) { FLUSH(); cur = sg[i]; }
            const float g = 1.f / (1.f + __expf(-(p[i] + bg)));
            s.x += hv[i].x; s.y += hv[i].y; s.z += hv[i].z; s.w += hv[i].w;
            gs.x = fmaf(g, hv[i].x, gs.x); gs.y = fmaf(g, hv[i].y, gs.y);
            gs.z = fmaf(g, hv[i].z, gs.z); gs.w = fmaf(g, hv[i].w, gs.w);
            mx.x = fmaxf(mx.x, hv[i].x);  mx.y = fmaxf(mx.y, hv[i].y);
            mx.z = fmaxf(mx.z, hv[i].z);  mx.w = fmaxf(mx.w, hv[i].w);
            cnt += 1.f;
        }
    }

    // tail
    for (; row < end; ++row) {
        float4 hv = reinterpret_cast<const float4*>(h + (size_t)row * H)[lane];
        int    sg = __ldg(&b[row]);
        if (sg != cur) { FLUSH(); cur = sg; }
        float p = hv.x * wg.x + hv.y * wg.y + hv.z * wg.z + hv.w * wg.w;
        p = warp_sum(p);
        const float g = 1.f / (1.f + __expf(-(p + bg)));
        s.x += hv.x; s.y += hv.y; s.z += hv.z; s.w += hv.w;
        gs.x = fmaf(g, hv.x, gs.x); gs.y = fmaf(g, hv.y, gs.y);
        gs.z = fmaf(g, hv.z, gs.z); gs.w = fmaf(g, hv.w, gs.w);
        mx.x = fmaxf(mx.x, hv.x);  mx.y = fmaxf(mx.y, hv.y);
        mx.z = fmaxf(mx.z, hv.z);  mx.w = fmaxf(mx.w, hv.w);
        cnt += 1.f;
    }

    FLUSH();
    #undef FLUSH
}

// ---------------- 3. per-rank projection: agg[B,4H] @ Wp[4H,H] + bp ----------------
// 256 threads: j = t&127, half = t>>7; each half sums 256 of the 512 k's.
__global__ __launch_bounds__(256) void proj_kernel(
    const float* __restrict__ Wp0, const float* __restrict__ bp0,
    const float* __restrict__ Wp1, const float* __restrict__ bp1,
    const float* __restrict__ Wp2, const float* __restrict__ bp2)
{
    const int rank = blockIdx.y;
    const int seg  = blockIdx.x;
    const int t    = threadIdx.x;
    const int j    = t & (H - 1);
    const int half = t >> 7;

    const float* Wp = (rank == 0) ? Wp0 : (rank == 1) ? Wp1 : Wp2;
    const float* bp = (rank == 0) ? bp0 : (rank == 1) ? bp1 : bp2;

    __shared__ float agg[4 * H];
    __shared__ float part[256];

    const int   base = (rank * NSEG + seg) * H;
    const float cnt  = g_cnt[rank * NSEG + seg];

    if (half == 0) {
        const float sv = g_sum[base + j];
        agg[j]     = sv;
        agg[H + j] = sv / fmaxf(cnt, 1.f);
    } else {
        const float mv = g_max[base + j];
        agg[2 * H + j] = (cnt > 0.f) ? mv : 0.f;
        agg[3 * H + j] = g_gsum[base + j];
    }
    __syncthreads();

    const int k0 = half * (2 * H);
    float a0 = 0.f, a1 = 0.f, a2 = 0.f, a3 = 0.f;
    #pragma unroll 4
    for (int k = 0; k < 2 * H; k += 4) {
        a0 = fmaf(agg[k0 + k + 0], Wp[(k0 + k + 0) * H + j], a0);
        a1 = fmaf(agg[k0 + k + 1], Wp[(k0 + k + 1) * H + j], a1);
        a2 = fmaf(agg[k0 + k + 2], Wp[(k0 + k + 2) * H + j], a2);
        a3 = fmaf(agg[k0 + k + 3], Wp[(k0 + k + 3) * H + j], a3);
    }
    part[t] = (a0 + a1) + (a2 + a3);
    __syncthreads();

    if (half == 0)
        g_r[base + j] = part[j] + part[H + j] + bp[j];
}

// ---------------- 4. head: concat -> LayerNorm -> SiLU -> W1 -> SiLU -> W2 ----------------
// 256 threads: half 0 does LN; both halves split the 3H-deep matvec.
__global__ __launch_bounds__(256) void head_kernel(
    const float* __restrict__ gamma, const float* __restrict__ beta,
    const float* __restrict__ W1,    const float* __restrict__ b1f,
    const float* __restrict__ W2,    const float* __restrict__ b2f,
    float* __restrict__ out)
{
    const int seg  = blockIdx.x;
    const int t    = threadIdx.x;
    const int j    = t & (H - 1);
    const int half = t >> 7;

    __shared__ float sx[3 * H];
    __shared__ float part[256];
    __shared__ float red[8];

    float v0 = 0.f, v1 = 0.f, v2 = 0.f;
    if (half == 0) {
        v0 = g_r[(0 * NSEG + seg) * H + j];
        v1 = g_r[(1 * NSEG + seg) * H + j];
        v2 = g_r[(2 * NSEG + seg) * H + j];
    }

    // mean (half-1 warps contribute 0)
    float loc = warp_sum(v0 + v1 + v2);
    if ((t & 31) == 0) red[t >> 5] = loc;
    __syncthreads();
    const float mu = (red[0] + red[1] + red[2] + red[3] +
                      red[4] + red[5] + red[6] + red[7]) * (1.f / (3.f * H));
    __syncthreads();

    // variance
    const float d0 = v0 - mu, d1 = v1 - mu, d2 = v2 - mu;
    float loc2 = warp_sum(half == 0 ? (d0 * d0 + d1 * d1 + d2 * d2) : 0.f);
    if ((t & 31) == 0) red[t >> 5] = loc2;
    __syncthreads();
    const float var  = (red[0] + red[1] + red[2] + red[3] +
                        red[4] + red[5] + red[6] + red[7]) * (1.f / (3.f * H));
    const float rstd = rsqrtf(var + LN_EPS);
    __syncthreads();

    if (half == 0) {
        float xn0 = d0 * rstd * gamma[j]         + beta[j];
        float xn1 = d1 * rstd * gamma[H + j]     + beta[H + j];
        float xn2 = d2 * rstd * gamma[2 * H + j] + beta[2 * H + j];
        sx[j]         = xn0 / (1.f + __expf(-xn0));
        sx[H + j]     = xn1 / (1.f + __expf(-xn1));
        sx[2 * H + j] = xn2 / (1.f + __expf(-xn2));
    }
    __syncthreads();

    // x @ W1 (+b1f): each half sums 192 of the 384 k's with 4 accumulators
    const int k0 = half * 192;
    float a0 = 0.f, a1 = 0.f, a2 = 0.f, a3 = 0.f;
    #pragma unroll 4
    for (int k = 0; k < 192; k += 4) {
        a0 = fmaf(sx[k0 + k + 0], W1[(k0 + k + 0) * H + j], a0);
        a1 = fmaf(sx[k0 + k + 1], W1[(k0 + k + 1) * H + j], a1);
        a2 = fmaf(sx[k0 + k + 2], W1[(k0 + k + 2) * H + j], a2);
        a3 = fmaf(sx[k0 + k + 3], W1[(k0 + k + 3) * H + j], a3);
    }
    part[t] = (a0 + a1) + (a2 + a3);
    __syncthreads();

    // SiLU -> dot with W2 -> out[seg]   (half 0 only)
    float o = 0.f;
    if (half == 0) {
        const float acc = part[j] + part[H + j] + b1f[j];
        const float x2  = acc / (1.f + __expf(-acc));
        o = x2 * W2[j];
    }
    o = warp_sum(o);
    if ((t & 31) == 0) red[t >> 5] = o;
    __syncthreads();
    if (t == 0)
        out[seg] = red[0] + red[1] + red[2] + red[3] + b2f[0];
}

// ---------------- launcher ----------------
extern "C" void kernel_launch(void* const* d_in, const int* in_sizes, int n_in,
                              void* d_out, int out_size)
{
    const float* h0  = (const float*)d_in[0];
    const float* h1  = (const float*)d_in[1];
    const float* h2  = (const float*)d_in[2];
    const int*   b0  = (const int*)  d_in[3];
    const int*   b1  = (const int*)  d_in[4];
    const int*   b2  = (const int*)  d_in[5];
    const float* Wg0 = (const float*)d_in[6];
    const float* bg0 = (const float*)d_in[7];
    const float* Wg1 = (const float*)d_in[8];
    const float* bg1 = (const float*)d_in[9];
    const float* Wg2 = (const float*)d_in[10];
    const float* bg2 = (const float*)d_in[11];
    const float* Wp0 = (const float*)d_in[12];
    const float* bp0 = (const float*)d_in[13];
    const float* Wp1 = (const float*)d_in[14];
    const float* bp1 = (const float*)d_in[15];
    const float* Wp2 = (const float*)d_in[16];
    const float* bp2 = (const float*)d_in[17];
    const float* gamma = (const float*)d_in[18];
    const float* beta  = (const float*)d_in[19];
    const float* W1    = (const float*)d_in[20];
    const float* b1f   = (const float*)d_in[21];
    const float* W2    = (const float*)d_in[22];
    const float* b2f   = (const float*)d_in[23];

    const int N0 = in_sizes[3];
    const int N1 = in_sizes[4];
    const int N2 = in_sizes[5];

    // 1. zero segment accumulators
    zero_kernel<<<(RANKS * NSEG * H + 255) / 256, 256>>>();

    // 2. single bandwidth pass over all node features
    dim3 gAgg(384, RANKS);
    agg_kernel<<<gAgg, 256>>>(h0, h1, h2, b0, b1, b2,
                              Wg0, Wg1, Wg2, bg0, bg1, bg2,
                              N0, N1, N2);

    // 3. per-rank pooled projection
    dim3 gProj(NSEG, RANKS);
    proj_kernel<<<gProj, 256>>>(Wp0, bp0, Wp1, bp1, Wp2, bp2);

    // 4. head
    head_kernel<<<NSEG, 256>>>(gamma, beta, W1, b1f, W2, b2f, (float*)d_out);
}